// round 2
// baseline (speedup 1.0000x reference)
#include <cuda_runtime.h>
#include <math.h>

#define HHv 83
#define WWv 25
#define AAv 9
#define N_ANCH (HHv*WWv*AAv)   /* 18675 */
#define BATCH 16
#define PRE 12000
#define POST 2000
#define MIN_SIZE 16.0f
#define NMS_T 0.7f
#define IMG_XF 1333.0f
#define IMG_YF 402.0f
#define FLIP_NEG_INF 0x007FFFFFu

__device__ float4   g_boxes[BATCH * N_ANCH];
__device__ unsigned g_skey [BATCH * N_ANCH];
__device__ float4   g_candBox[BATCH * PRE];
__device__ int      g_candCount[BATCH];

__device__ __forceinline__ unsigned flipf(float f){
    unsigned u = __float_as_uint(f);
    return (u & 0x80000000u) ? ~u : (u | 0x80000000u);
}

// ---------------------------------------------------------------- K1: decode
__global__ void k_decode(const float4* __restrict__ anchors,
                         const float*  __restrict__ cls,
                         const float4* __restrict__ pred)
{
    int t = blockIdx.x*blockDim.x + threadIdx.x;
    if (t >= BATCH*N_ANCH) return;
    int b = t / N_ANCH, i = t - b*N_ANCH;

    float4 a = anchors[i];
    float ah  = __fsub_rn(a.w, a.y);
    float aw  = __fsub_rn(a.z, a.x);
    float acy = __fadd_rn(a.y, __fmul_rn(0.5f, ah));
    float acx = __fadd_rn(a.x, __fmul_rn(0.5f, aw));

    float4 p = pred[t];   // dx, dy, dw, dh
    float cy = __fadd_rn(__fmul_rn(p.y, ah), acy);
    float cx = __fadd_rn(__fmul_rn(p.x, aw), acx);
    float eh = (float)exp((double)p.w);
    float ew = (float)exp((double)p.z);
    float h  = __fmul_rn(eh, ah);
    float w  = __fmul_rn(ew, aw);

    float hw = __fmul_rn(0.5f, w);
    float hh = __fmul_rn(0.5f, h);
    float x1 = fminf(fmaxf(__fsub_rn(cx, hw), 0.f), IMG_XF);
    float y1 = fminf(fmaxf(__fsub_rn(cy, hh), 0.f), IMG_YF);
    float x2 = fminf(fmaxf(__fadd_rn(cx, hw), 0.f), IMG_XF);
    float y2 = fminf(fmaxf(__fadd_rn(cy, hh), 0.f), IMG_YF);

    g_boxes[t] = make_float4(x1, y1, x2, y2);

    bool valid = (__fsub_rn(y2, y1) >= MIN_SIZE) && (__fsub_rn(x2, x1) >= MIN_SIZE);
    float s = valid ? cls[b*(2*N_ANCH) + 2*i + 1] : -INFINITY;
    g_skey[t] = flipf(s);
}

// -------------------------------------------- K2: exact top-PRE select + compact
__global__ void k_select()
{
    int b = blockIdx.x;
    const unsigned* skey = g_skey + b*N_ANCH;
    const int BD = blockDim.x;
    int tid = threadIdx.x;

    __shared__ int      hist[2048];
    __shared__ unsigned s_pfx, s_T;
    __shared__ int      s_r, s_cEq, s_binI, s_rr, s_eqN, s_Tidx;
    __shared__ int      s_eqIdx[32];

    // ---- pass 1: bits [21,32)
    for (int j=tid;j<2048;j+=BD) hist[j]=0;
    __syncthreads();
    for (int i=tid;i<N_ANCH;i+=BD) atomicAdd(&hist[skey[i]>>21], 1);
    __syncthreads();
    if (tid==0){
        int cum=0, r=PRE; unsigned b0=0;
        for (int bin=2047; bin>=0; --bin){
            int c=hist[bin];
            if (cum+c>=PRE){ b0=(unsigned)bin; r=PRE-cum; break; }
            cum+=c;
        }
        s_pfx=b0; s_r=r;
    }
    __syncthreads();
    unsigned b0 = s_pfx; int r = s_r;

    // ---- pass 2: bits [10,21)
    for (int j=tid;j<2048;j+=BD) hist[j]=0;
    __syncthreads();
    for (int i=tid;i<N_ANCH;i+=BD){
        unsigned k=skey[i];
        if ((k>>21)==b0) atomicAdd(&hist[(k>>10)&0x7FFu],1);
    }
    __syncthreads();
    if (tid==0){
        int cum=0; unsigned b1=0; int rr=r;
        for (int bin=2047;bin>=0;--bin){
            int c=hist[bin];
            if (cum+c>=r){ b1=(unsigned)bin; rr=r-cum; break; }
            cum+=c;
        }
        s_pfx = (b0<<11)|b1; s_r=rr;
    }
    __syncthreads();
    unsigned pfx = s_pfx; r = s_r;

    // ---- pass 3: bits [0,10)
    for (int j=tid;j<1024;j+=BD) hist[j]=0;
    __syncthreads();
    for (int i=tid;i<N_ANCH;i+=BD){
        unsigned k=skey[i];
        if ((k>>10)==pfx) atomicAdd(&hist[k&0x3FFu],1);
    }
    __syncthreads();
    if (tid==0){
        int cum=0; unsigned b2=0; int rr=r; int cEq=0;
        for (int bin=1023;bin>=0;--bin){
            int c=hist[bin];
            if (cum+c>=r){ b2=(unsigned)bin; rr=r-cum; cEq=c; break; }
            cum+=c;
        }
        s_T = (pfx<<10)|b2; s_r=rr; s_cEq=cEq;
    }
    __syncthreads();
    unsigned T = s_T; r = s_r; int cEq = s_cEq;

    // ---- tie-break among skey==T by ascending anchor index
    int Tidx;
    if (r >= cEq){
        Tidx = N_ANCH;  // include all equals
    } else {
        for (int j=tid;j<2048;j+=BD) hist[j]=0;
        __syncthreads();
        for (int i=tid;i<N_ANCH;i+=BD)
            if (skey[i]==T) atomicAdd(&hist[i>>4],1);
        __syncthreads();
        if (tid==0){
            int cum=0, binI=0, rr=r;
            for (int bin=0;bin<2048;++bin){
                int c=hist[bin];
                if (cum+c>=r){ binI=bin; rr=r-cum; break; }
                cum+=c;
            }
            s_binI=binI; s_rr=rr; s_eqN=0;
        }
        __syncthreads();
        int binI=s_binI;
        for (int i=tid;i<N_ANCH;i+=BD)
            if (skey[i]==T && (i>>4)==binI){
                int p=atomicAdd(&s_eqN,1);
                s_eqIdx[p]=i;
            }
        __syncthreads();
        if (tid==0){
            int n=s_eqN, need=s_rr;
            for (int a2=0;a2<n;a2++)
                for (int b2=a2+1;b2<n;b2++)
                    if (s_eqIdx[b2]<s_eqIdx[a2]){
                        int tmp=s_eqIdx[a2]; s_eqIdx[a2]=s_eqIdx[b2]; s_eqIdx[b2]=tmp;
                    }
            s_Tidx = s_eqIdx[need-1];
        }
        __syncthreads();
        Tidx = s_Tidx;
    }

    // ---- compact valid+selected candidates, DESCENDING anchor index
    __shared__ int s_wcnt[8], s_wbase[8], s_total;
    if (tid==0) s_total=0;
    __syncthreads();

    const float4* boxes = g_boxes   + b*N_ANCH;
    float4*       cand  = g_candBox + b*PRE;
    int lane = tid & 31, wid = tid>>5, nw = BD>>5;
    int nCh = (N_ANCH + BD - 1)/BD;

    for (int c=0;c<nCh;c++){
        int pos = c*BD + tid;
        int i = N_ANCH-1-pos;
        bool pred=false;
        if (i>=0){
            unsigned k = skey[i];
            bool valid = (k != FLIP_NEG_INF);
            bool sel   = (k > T) || (k==T && i<=Tidx);
            pred = valid && sel;
        }
        unsigned bal = __ballot_sync(0xffffffffu, pred);
        if (lane==0) s_wcnt[wid]=__popc(bal);
        __syncthreads();
        if (tid==0){
            int acc=s_total;
            for (int w2=0;w2<nw;w2++){ s_wbase[w2]=acc; acc+=s_wcnt[w2]; }
            s_total=acc;
        }
        __syncthreads();
        if (pred){
            int p = s_wbase[wid] + __popc(bal & ((1u<<lane)-1u));
            cand[p] = boxes[i];
        }
        __syncthreads();
    }
    if (tid==0) g_candCount[b]=s_total;
}

// ---------------------------------------------------------------- K3: greedy NMS
__device__ __forceinline__ bool iou_gt(const float4& A, float aA,
                                       const float4& Bx, float aB)
{
    float xx1=fmaxf(A.x,Bx.x), yy1=fmaxf(A.y,Bx.y);
    float xx2=fminf(A.z,Bx.z), yy2=fminf(A.w,Bx.w);
    float iw=__fadd_rn(__fsub_rn(xx2,xx1),1.f);
    float ih=__fadd_rn(__fsub_rn(yy2,yy1),1.f);
    float inter=__fmul_rn(fmaxf(iw,0.f), fmaxf(ih,0.f));
    float uni = __fsub_rn(__fadd_rn(aA,aB), inter);
    float ovr = __fdiv_rn(inter, uni);
    return ovr > NMS_T;
}

__device__ __forceinline__ float areaf(const float4& bx){
    return __fmul_rn(__fadd_rn(__fsub_rn(bx.z,bx.x),1.f),
                     __fadd_rn(__fsub_rn(bx.w,bx.y),1.f));
}

// Shared-memory layout (bytes)
#define SOFF_BOX    0
#define SOFF_ALIVE  192000                 /* 12000*16 */
#define SOFF_Q      204032                 /* ALIVE + 12032 */
#define SOFF_PICK   208256                 /* Q + 1056*4 = 4224 */
#define SOFF_PAREA  208768                 /* PICK + 512 */
#define SOFF_MAT    208896
#define SOFF_NEW    209024
#define SMEM_NMS    209280

__global__ void __launch_bounds__(1024)
k_nms(float* __restrict__ outRois, float* __restrict__ outMask, int writeMask)
{
    extern __shared__ unsigned char sm[];
    float4*        s_box   = (float4*)(sm + SOFF_BOX);
    unsigned char* s_alive = sm + SOFF_ALIVE;
    int*           s_q     = (int*)(sm + SOFF_Q);
    float4*        s_pick  = (float4*)(sm + SOFF_PICK);
    float*         s_parea = (float*)(sm + SOFF_PAREA);
    unsigned*      s_mat   = (unsigned*)(sm + SOFF_MAT);
    int*           s_new   = (int*)(sm + SOFF_NEW);

    __shared__ int s_qn, s_kept, s_nn, s_cursor;
    __shared__ int s_wcnt[32], s_wbase[32];

    int b   = blockIdx.x;
    int tid = threadIdx.x;
    int nc  = g_candCount[b];
    const float4* cand = g_candBox + b*PRE;
    int lane = tid & 31, wid = tid >> 5;

    for (int i=tid;i<nc;i+=1024){ s_box[i]=cand[i]; s_alive[i]=1; }
    if (tid==0){ s_kept=0; s_cursor=0; }
    __syncthreads();

    while (true){
        int kept = s_kept;
        if (kept >= POST) break;

        // ---- gather next (up to) 32 alive candidates, in order
        if (tid==0) s_qn=0;
        __syncthreads();
        while (true){
            int qn = s_qn, cur = s_cursor;
            if (qn >= 32 || cur >= nc) break;
            int i = cur + tid;
            bool pred = (i < nc) && s_alive[i];
            unsigned bal = __ballot_sync(0xffffffffu, pred);
            if (lane==0) s_wcnt[wid]=__popc(bal);
            __syncthreads();
            if (tid==0){
                int acc=s_qn;
                for (int w2=0;w2<32;w2++){ s_wbase[w2]=acc; acc+=s_wcnt[w2]; }
                s_qn = acc;
                s_cursor = cur + 1024;
            }
            __syncthreads();
            if (pred){
                int p = s_wbase[wid] + __popc(bal & ((1u<<lane)-1u));
                s_q[p] = i;
            }
            __syncthreads();
        }
        int qn = s_qn;
        int m  = qn < 32 ? qn : 32;
        if (m == 0) break;

        // ---- load picks, mark decided, reset cursor past pick window
        if (tid < m){
            int i = s_q[tid];
            float4 bx = s_box[i];
            s_pick[tid]  = bx;
            s_parea[tid] = areaf(bx);
            s_alive[i]   = 0;
        }
        if (tid==0 && qn >= 32) s_cursor = s_q[31] + 1;
        __syncthreads();

        // ---- 32x32 forward suppression matrix: 1 IoU per thread
        {
            int c = wid, c2 = lane;
            bool sup = false;
            if (c < m && c2 < m && c2 > c)
                sup = iou_gt(s_pick[c], s_parea[c], s_pick[c2], s_parea[c2]);
            unsigned bal = __ballot_sync(0xffffffffu, sup);
            if (lane==0 && c < m) s_mat[c] = bal;
        }
        __syncthreads();

        // ---- serial greedy resolve within the batch
        if (tid==0){
            unsigned sup = 0u; int nn = 0;
            for (int c=0;c<m;c++){
                if (!((sup>>c)&1u)){
                    s_new[nn++] = c;
                    sup |= s_mat[c];
                    if (kept + nn == POST) break;
                }
            }
            s_nn = nn;
        }
        __syncthreads();
        int nn = s_nn;

        // ---- compact new keeps to front of s_pick / s_parea, write outputs
        float4 kb; float kaV = 0.f;
        if (tid < nn){ int cc = s_new[tid]; kb = s_pick[cc]; kaV = s_parea[cc]; }
        __syncthreads();
        if (tid < nn){
            s_pick[tid]  = kb;
            s_parea[tid] = kaV;
            int row = b*POST + kept + tid;
            ((float4*)outRois)[row] = kb;
            if (writeMask) outMask[row] = 1.0f;
        }
        __syncthreads();

        // ---- forward sweep: new keeps suppress alive candidates ahead
        int start = s_q[m-1] + 1;
        for (int i = start + tid; i < nc; i += 1024){
            if (!s_alive[i]) continue;
            float4 A = s_box[i];
            float aA = areaf(A);
            bool dead = false;
            #pragma unroll 1
            for (int j=0;j<nn;j++){
                float aB = s_parea[j];
                float amin = fminf(aA,aB), amax = fmaxf(aA,aB);
                if (amin < 0.695f*amax) continue;   // IoU <= amin/amax < 0.7 (safe margin)
                if (iou_gt(s_pick[j], aB, A, aA)){ dead = true; break; }
            }
            if (dead) s_alive[i] = 0;
        }
        if (tid==0) s_kept = kept + nn;
        __syncthreads();
    }

    // ---- zero-fill tail
    int kept = s_kept;
    for (int rrow = kept + tid; rrow < POST; rrow += 1024){
        int row = b*POST + rrow;
        ((float4*)outRois)[row] = make_float4(0.f,0.f,0.f,0.f);
        if (writeMask) outMask[row] = 0.f;
    }
}

// ---------------------------------------------------------------- launch
extern "C" void kernel_launch(void* const* d_in, const int* in_sizes, int n_in,
                              void* d_out, int out_size)
{
    (void)in_sizes; (void)n_in;
    const float4* anchors = (const float4*)d_in[0];
    const float*  cls     = (const float*)d_in[1];
    const float4* pred    = (const float4*)d_in[2];
    float* out = (float*)d_out;

    cudaFuncSetAttribute(k_nms, cudaFuncAttributeMaxDynamicSharedMemorySize, SMEM_NMS);

    int total = BATCH*N_ANCH;
    k_decode<<<(total+255)/256, 256>>>(anchors, cls, pred);
    k_select<<<BATCH, 256>>>();

    int writeMask = (out_size >= BATCH*POST*5) ? 1 : 0;
    k_nms<<<BATCH, 1024, SMEM_NMS>>>(out, out + BATCH*POST*4, writeMask);
}

// round 3
// speedup vs baseline: 6.6480x; 6.6480x over previous
#include <cuda_runtime.h>
#include <math.h>

#define HHv 83
#define WWv 25
#define AAv 9
#define N_ANCH (HHv*WWv*AAv)   /* 18675 */
#define BATCH 16
#define PRE 12000
#define POST 2000
#define MIN_SIZE 16.0f
#define NMS_T 0.7f
#define IMG_XF 1333.0f
#define IMG_YF 402.0f
#define FLIP_NEG_INF 0x007FFFFFu

__device__ float4   g_boxes[BATCH * N_ANCH];
__device__ unsigned g_skey [BATCH * N_ANCH];
__device__ float4   g_candBox[BATCH * PRE];
__device__ int      g_candCount[BATCH];

__device__ __forceinline__ unsigned flipf(float f){
    unsigned u = __float_as_uint(f);
    return (u & 0x80000000u) ? ~u : (u | 0x80000000u);
}

// ---------------------------------------------------------------- K1: decode
__global__ void k_decode(const float4* __restrict__ anchors,
                         const float*  __restrict__ cls,
                         const float4* __restrict__ pred)
{
    int t = blockIdx.x*blockDim.x + threadIdx.x;
    if (t >= BATCH*N_ANCH) return;
    int b = t / N_ANCH, i = t - b*N_ANCH;

    float4 a = anchors[i];
    float ah  = __fsub_rn(a.w, a.y);
    float aw  = __fsub_rn(a.z, a.x);
    float acy = __fadd_rn(a.y, __fmul_rn(0.5f, ah));
    float acx = __fadd_rn(a.x, __fmul_rn(0.5f, aw));

    float4 p = pred[t];   // dx, dy, dw, dh
    float cy = __fadd_rn(__fmul_rn(p.y, ah), acy);
    float cx = __fadd_rn(__fmul_rn(p.x, aw), acx);
    float eh = (float)exp((double)p.w);
    float ew = (float)exp((double)p.z);
    float h  = __fmul_rn(eh, ah);
    float w  = __fmul_rn(ew, aw);

    float hw = __fmul_rn(0.5f, w);
    float hh = __fmul_rn(0.5f, h);
    float x1 = fminf(fmaxf(__fsub_rn(cx, hw), 0.f), IMG_XF);
    float y1 = fminf(fmaxf(__fsub_rn(cy, hh), 0.f), IMG_YF);
    float x2 = fminf(fmaxf(__fadd_rn(cx, hw), 0.f), IMG_XF);
    float y2 = fminf(fmaxf(__fadd_rn(cy, hh), 0.f), IMG_YF);

    g_boxes[t] = make_float4(x1, y1, x2, y2);

    bool valid = (__fsub_rn(y2, y1) >= MIN_SIZE) && (__fsub_rn(x2, x1) >= MIN_SIZE);
    float s = valid ? cls[b*(2*N_ANCH) + 2*i + 1] : -INFINITY;
    g_skey[t] = flipf(s);
}

// -------------------------------------------- K2: exact top-PRE select + compact
__global__ void __launch_bounds__(1024) k_select()
{
    int b = blockIdx.x;
    const unsigned* skey = g_skey + b*N_ANCH;
    const int BD = 1024;
    int tid = threadIdx.x;

    __shared__ int      hist[2048];
    __shared__ unsigned s_pfx, s_T;
    __shared__ int      s_r, s_cEq, s_binI, s_rr, s_eqN, s_Tidx;
    __shared__ int      s_eqIdx[32];

    // ---- pass 1: bits [21,32)
    for (int j=tid;j<2048;j+=BD) hist[j]=0;
    __syncthreads();
    for (int i=tid;i<N_ANCH;i+=BD) atomicAdd(&hist[skey[i]>>21], 1);
    __syncthreads();
    if (tid==0){
        int cum=0, r=PRE; unsigned b0=0;
        for (int bin=2047; bin>=0; --bin){
            int c=hist[bin];
            if (cum+c>=PRE){ b0=(unsigned)bin; r=PRE-cum; break; }
            cum+=c;
        }
        s_pfx=b0; s_r=r;
    }
    __syncthreads();
    unsigned b0 = s_pfx; int r = s_r;

    // ---- pass 2: bits [10,21)
    for (int j=tid;j<2048;j+=BD) hist[j]=0;
    __syncthreads();
    for (int i=tid;i<N_ANCH;i+=BD){
        unsigned k=skey[i];
        if ((k>>21)==b0) atomicAdd(&hist[(k>>10)&0x7FFu],1);
    }
    __syncthreads();
    if (tid==0){
        int cum=0; unsigned b1=0; int rr=r;
        for (int bin=2047;bin>=0;--bin){
            int c=hist[bin];
            if (cum+c>=r){ b1=(unsigned)bin; rr=r-cum; break; }
            cum+=c;
        }
        s_pfx = (b0<<11)|b1; s_r=rr;
    }
    __syncthreads();
    unsigned pfx = s_pfx; r = s_r;

    // ---- pass 3: bits [0,10)
    for (int j=tid;j<1024;j+=BD) hist[j]=0;
    __syncthreads();
    for (int i=tid;i<N_ANCH;i+=BD){
        unsigned k=skey[i];
        if ((k>>10)==pfx) atomicAdd(&hist[k&0x3FFu],1);
    }
    __syncthreads();
    if (tid==0){
        int cum=0; unsigned b2=0; int rr=r; int cEq=0;
        for (int bin=1023;bin>=0;--bin){
            int c=hist[bin];
            if (cum+c>=r){ b2=(unsigned)bin; rr=r-cum; cEq=c; break; }
            cum+=c;
        }
        s_T = (pfx<<10)|b2; s_r=rr; s_cEq=cEq;
    }
    __syncthreads();
    unsigned T = s_T; r = s_r; int cEq = s_cEq;

    // ---- tie-break among skey==T by ascending anchor index
    int Tidx;
    if (r >= cEq){
        Tidx = N_ANCH;  // include all equals
    } else {
        for (int j=tid;j<2048;j+=BD) hist[j]=0;
        __syncthreads();
        for (int i=tid;i<N_ANCH;i+=BD)
            if (skey[i]==T) atomicAdd(&hist[i>>4],1);
        __syncthreads();
        if (tid==0){
            int cum=0, binI=0, rr=r;
            for (int bin=0;bin<2048;++bin){
                int c=hist[bin];
                if (cum+c>=r){ binI=bin; rr=r-cum; break; }
                cum+=c;
            }
            s_binI=binI; s_rr=rr; s_eqN=0;
        }
        __syncthreads();
        int binI=s_binI;
        for (int i=tid;i<N_ANCH;i+=BD)
            if (skey[i]==T && (i>>4)==binI){
                int p=atomicAdd(&s_eqN,1);
                s_eqIdx[p]=i;
            }
        __syncthreads();
        if (tid==0){
            int n=s_eqN, need=s_rr;
            for (int a2=0;a2<n;a2++)
                for (int b2=a2+1;b2<n;b2++)
                    if (s_eqIdx[b2]<s_eqIdx[a2]){
                        int tmp=s_eqIdx[a2]; s_eqIdx[a2]=s_eqIdx[b2]; s_eqIdx[b2]=tmp;
                    }
            s_Tidx = s_eqIdx[need-1];
        }
        __syncthreads();
        Tidx = s_Tidx;
    }

    // ---- compact valid+selected candidates, DESCENDING anchor index
    __shared__ int s_wcnt[32], s_wbase[32], s_total;
    if (tid==0) s_total=0;
    __syncthreads();

    const float4* boxes = g_boxes   + b*N_ANCH;
    float4*       cand  = g_candBox + b*PRE;
    int lane = tid & 31, wid = tid>>5;
    int nCh = (N_ANCH + BD - 1)/BD;

    for (int c=0;c<nCh;c++){
        int pos = c*BD + tid;
        int i = N_ANCH-1-pos;
        bool pred=false;
        if (i>=0){
            unsigned k = skey[i];
            bool valid = (k != FLIP_NEG_INF);
            bool sel   = (k > T) || (k==T && i<=Tidx);
            pred = valid && sel;
        }
        unsigned bal = __ballot_sync(0xffffffffu, pred);
        if (lane==0) s_wcnt[wid]=__popc(bal);
        __syncthreads();
        if (tid==0){
            int acc=s_total;
            for (int w2=0;w2<32;w2++){ s_wbase[w2]=acc; acc+=s_wcnt[w2]; }
            s_total=acc;
        }
        __syncthreads();
        if (pred){
            int p = s_wbase[wid] + __popc(bal & ((1u<<lane)-1u));
            cand[p] = boxes[i];
        }
        __syncthreads();
    }
    if (tid==0) g_candCount[b]=s_total;
}

// ---------------------------------------------------------------- K3: greedy NMS
__device__ __forceinline__ bool iou_gt(const float4& A, float aA,
                                       const float4& Bx, float aB)
{
    float xx1=fmaxf(A.x,Bx.x), yy1=fmaxf(A.y,Bx.y);
    float xx2=fminf(A.z,Bx.z), yy2=fminf(A.w,Bx.w);
    float iw=__fadd_rn(__fsub_rn(xx2,xx1),1.f);
    float ih=__fadd_rn(__fsub_rn(yy2,yy1),1.f);
    float inter=__fmul_rn(fmaxf(iw,0.f), fmaxf(ih,0.f));
    float uni = __fsub_rn(__fadd_rn(aA,aB), inter);
    float ovr = __fdiv_rn(inter, uni);
    return ovr > NMS_T;
}

__device__ __forceinline__ float areaf(const float4& bx){
    return __fmul_rn(__fadd_rn(__fsub_rn(bx.z,bx.x),1.f),
                     __fadd_rn(__fsub_rn(bx.w,bx.y),1.f));
}

__global__ void __launch_bounds__(1024)
k_nms(float* __restrict__ outRois, float* __restrict__ outMask, int writeMask)
{
    __shared__ float4   kb[POST];
    __shared__ float    ka[POST];
    __shared__ float4   cbox[32];
    __shared__ float    carea[32];
    __shared__ unsigned s_supw[32];
    __shared__ unsigned s_mat[32];
    __shared__ int      s_new[32];
    __shared__ int      s_nn, s_kept;

    int b    = blockIdx.x;
    int tid  = threadIdx.x;
    int lane = tid & 31;
    int wid  = tid >> 5;
    int nc   = g_candCount[b];
    const float4* cand = g_candBox + b*PRE;

    if (tid==0) s_kept = 0;
    __syncthreads();

    for (int start=0; start<nc; start+=32){
        int kept = s_kept;
        if (kept >= POST) break;
        int n = min(32, nc-start);

        // ---- phase A: load chunk candidates
        if (tid < n){
            float4 bx = cand[start+tid];
            cbox[tid]  = bx;
            carea[tid] = areaf(bx);
        }
        __syncthreads();

        // ---- phase B1: intra-chunk 32x32 forward matrix, 1 IoU per thread
        {
            bool sup = false;
            if (wid < n && lane > wid && lane < n)
                sup = iou_gt(cbox[wid], carea[wid], cbox[lane], carea[lane]);
            unsigned mb = __ballot_sync(0xffffffffu, sup);
            if (lane==0) s_mat[wid] = mb;
        }

        // ---- phase B2: candidate(lane) vs kept list (strided by warp)
        {
            bool f = (lane >= n);
            float4 A = cbox[lane];
            float aA = carea[lane];
            int k = wid;
            #pragma unroll 1
            while (k < kept){
                #pragma unroll 8
                for (int u=0; u<8; u++){
                    if (k < kept && !f){
                        float aB = ka[k];
                        if (fminf(aA,aB) >= __fmul_rn(0.695f, fmaxf(aA,aB)))
                            f = iou_gt(A, aA, kb[k], aB);
                    }
                    k += 32;
                }
                if (__all_sync(0xffffffffu, f)) break;
            }
            unsigned sb = __ballot_sync(0xffffffffu, f);
            if (lane==0) s_supw[wid] = sb;
        }
        __syncthreads();

        // ---- phase C: serial greedy resolve
        if (tid==0){
            unsigned sup = 0u;
            #pragma unroll
            for (int w=0; w<32; w++) sup |= s_supw[w];
            int nn = 0;
            for (int c=0; c<n; c++){
                if (!((sup>>c)&1u)){
                    s_new[nn++] = c;
                    sup |= s_mat[c];
                    if (kept + nn == POST) break;
                }
            }
            s_nn = nn;
            s_kept = kept + nn;
        }
        __syncthreads();

        // ---- phase D: append keeps + write outputs
        int nn = s_nn;
        if (tid < nn){
            int cc = s_new[tid];
            float4 bx = cbox[cc];
            kb[kept+tid] = bx;
            ka[kept+tid] = carea[cc];
            int row = b*POST + kept + tid;
            ((float4*)outRois)[row] = bx;
            if (writeMask) outMask[row] = 1.0f;
        }
        __syncthreads();
    }

    // ---- zero-fill tail
    int kept = s_kept;
    for (int rrow = kept + tid; rrow < POST; rrow += 1024){
        int row = b*POST + rrow;
        ((float4*)outRois)[row] = make_float4(0.f,0.f,0.f,0.f);
        if (writeMask) outMask[row] = 0.f;
    }
}

// ---------------------------------------------------------------- launch
extern "C" void kernel_launch(void* const* d_in, const int* in_sizes, int n_in,
                              void* d_out, int out_size)
{
    (void)in_sizes; (void)n_in;
    const float4* anchors = (const float4*)d_in[0];
    const float*  cls     = (const float*)d_in[1];
    const float4* pred    = (const float4*)d_in[2];
    float* out = (float*)d_out;

    int total = BATCH*N_ANCH;
    k_decode<<<(total+255)/256, 256>>>(anchors, cls, pred);
    k_select<<<BATCH, 1024>>>();

    int writeMask = (out_size >= BATCH*POST*5) ? 1 : 0;
    k_nms<<<BATCH, 1024>>>(out, out + BATCH*POST*4, writeMask);
}